// round 15
// baseline (speedup 1.0000x reference)
#include <cuda_runtime.h>
#include <cuda_fp16.h>
#include <math.h>
#include <stdint.h>

#define NN0 100000
#define NN1 150000
#define NN2 50000
#define NNZ00 1600000
#define NNZ12 200000
#define DD 128

#define NB0 98              // ceil(NN0/1024)
#define NB2 49              // ceil(NN2/1024)
#define NBT (NB0 + NB2)     // 147 <= 148 SMs: co-resident at occ 1

// ---------------- device scratch (zero-initialized; spmm zero-blocks restore) ----------------
__device__ uint2 g_h0[(size_t)NN0 * 32];       // relu(x0) fp16
__device__ uint2 g_h1[(size_t)NN1 * 32];       // relu(x1) fp16
__device__ uint2 g_S0h[(size_t)NN0 * 32];      // S0 fp16
__device__ uint2 g_S2h[(size_t)NN2 * 32];      // S2 fp16
__device__ __half g_WT0[DD * DD];              // W0^T fp16 [n][k]
__device__ __half g_WT2[DD * DD];              // W12^T fp16 [n][k]
__device__ __align__(16) int g_rp0[NN0 + 4];
__device__ __align__(16) int g_fill0[NN0];     // counts -> cursors (re-zeroed in spmm)
__device__ __align__(16) int g_rp2[NN2 + 4];
__device__ __align__(16) int g_fill2[NN2];
__device__ int  g_flagA[NBT];                  // lookback flags (re-zeroed in spmm)
__device__ __align__(16) int2 g_e0[NNZ00];
__device__ __align__(16) int2 g_e2[NNZ12];

// ---------------- #1: histogram ----------------
__global__ void hist2_kernel(const int* __restrict__ r00, const int* __restrict__ r12) {
    int i = blockIdx.x * blockDim.x + threadIdx.x;
    if (i < NNZ00) {
        atomicAdd(&g_fill0[r00[i]], 1);
    } else {
        int j = i - NNZ00;
        if (j < NNZ12) atomicAdd(&g_fill2[r12[j]], 1);
    }
}

// ---------------- #2: conversions + W transpose + out_x1 + decoupled-lookback scan ----------------
#define NAT (NBT * 1024)
__global__ __launch_bounds__(1024, 1)
void convscan_kernel(const float* __restrict__ x0, const float* __restrict__ x1,
                     const float* __restrict__ W0, const float* __restrict__ W12,
                     float* __restrict__ out_x1) {
    __shared__ int wsum[32];
    __shared__ int sh_agg;
    __shared__ int s_off;
    int tid  = threadIdx.x;
    int gtid = blockIdx.x * 1024 + tid;
    int b = blockIdx.x;

    int* cntfill; int* rp; int R; int base0; int lastcb;
    if (b < NB0) { cntfill = g_fill0; rp = g_rp0; R = NN0; base0 = 0;   lastcb = NB0 - 1; }
    else         { cntfill = g_fill2; rp = g_rp2; R = NN2; base0 = NB0; lastcb = NB2 - 1; }
    int cb  = b - base0;
    int idx = cb * 1024 + tid;

    // --- phase 1: block-local scan of counts + EARLY aggregate publish ---
    int c = (idx < R) ? cntfill[idx] : 0;
    int lane = tid & 31, w = tid >> 5;
    int inc = c;
    #pragma unroll
    for (int off = 1; off < 32; off <<= 1) {
        int v = __shfl_up_sync(0xffffffffu, inc, off);
        if (lane >= off) inc += v;
    }
    if (lane == 31) wsum[w] = inc;
    if (tid == 0) s_off = 0;
    __syncthreads();
    if (w == 0) {
        int v = wsum[lane];
        int winc = v;
        #pragma unroll
        for (int off = 1; off < 32; off <<= 1) {
            int u = __shfl_up_sync(0xffffffffu, winc, off);
            if (lane >= off) winc += u;
        }
        wsum[lane] = winc - v;
        if (lane == 31) {
            sh_agg = winc;
            atomicExch(&g_flagA[b], winc + 1);
        }
    }
    __syncthreads();

    // --- phase 2: bulk conversions (streaming hints: x reads and out_x1 write are single-use) ---
    for (int i = gtid; i < DD * DD; i += NAT) {
        int r = i >> 7, cc = i & 127;
        g_WT0[cc * DD + r] = __float2half_rn(W0[i]);
        g_WT2[cc * DD + r] = __float2half_rn(W12[i]);
    }
    for (int i = gtid; i < NN0 * 32; i += NAT) {
        float4 v = __ldcs((const float4*)x0 + i);
        half2 p0 = __floats2half2_rn(fmaxf(v.x, 0.f), fmaxf(v.y, 0.f));
        half2 p1 = __floats2half2_rn(fmaxf(v.z, 0.f), fmaxf(v.w, 0.f));
        g_h0[i] = make_uint2(*(uint32_t*)&p0, *(uint32_t*)&p1);
    }
    for (int i = gtid; i < NN1 * 32; i += NAT) {
        float4 v = __ldcs((const float4*)x1 + i);
        v.x = fmaxf(v.x, 0.f); v.y = fmaxf(v.y, 0.f);
        v.z = fmaxf(v.z, 0.f); v.w = fmaxf(v.w, 0.f);
        __stcs((float4*)out_x1 + i, v);
        half2 p0 = __floats2half2_rn(v.x, v.y);
        half2 p1 = __floats2half2_rn(v.z, v.w);
        g_h1[i] = make_uint2(*(uint32_t*)&p0, *(uint32_t*)&p1);
    }

    // --- phase 3: lookback (flags long published) ---
    int local = 0;
    for (int j = base0 + tid; j < b; j += 1024) {
        int v;
        while ((v = *(volatile int*)&g_flagA[j]) == 0) __nanosleep(20);
        local += v - 1;
    }
    if (local) atomicAdd(&s_off, local);
    __syncthreads();
    int off = s_off;

    if (idx < R) {
        int v = off + wsum[w] + inc - c;
        rp[idx]      = v;
        cntfill[idx] = v;
    }
    if (tid == 0 && cb == lastcb) rp[R] = off + sh_agg;
}

// ---------------- #3: CSR fill ----------------
__global__ void fill2_kernel(const int* __restrict__ r00, const int* __restrict__ c00,
                             const float* __restrict__ v00,
                             const int* __restrict__ r12, const int* __restrict__ c12,
                             const float* __restrict__ v12) {
    int i = blockIdx.x * blockDim.x + threadIdx.x;
    if (i < NNZ00) {
        int p = atomicAdd(&g_fill0[r00[i]], 1);
        g_e0[p] = make_int2(c00[i], __float_as_int(v00[i]));
    } else {
        int j = i - NNZ00;
        if (j < NNZ12) {
            int p = atomicAdd(&g_fill2[r12[j]], 1);
            g_e2[p] = make_int2(c12[j], __float_as_int(v12[j]));
        }
    }
}

// ---------------- #4: SpMM (profiled): warp per TWO interleaved rows ----------------
#define WPAIR0 (NN0 / 2)             // 50000 warps for matrix 0
#define WPAIR2 (NN2 / 2)             // 25000 warps for matrix 2
#define SPBLK ((WPAIR0 + WPAIR2) * 32 / 256)   // 9375 compute blocks
#define ZTOT  (NN0 + NN2 + NBT)
#define ZBLK  ((ZTOT + 255) / 256)   // 587 zero blocks appended

__device__ __forceinline__ void accum4(float4& acc, uint2 q, float v) {
    float2 f0 = __half22float2(*(half2*)&q.x);
    float2 f1 = __half22float2(*(half2*)&q.y);
    acc.x = fmaf(v, f0.x, acc.x);
    acc.y = fmaf(v, f0.y, acc.y);
    acc.z = fmaf(v, f1.x, acc.z);
    acc.w = fmaf(v, f1.y, acc.w);
}

// gather 4 edges of one row into acc (no loop): helper for interleaved body
__device__ __forceinline__ void gath4(const char* xl, const int2* __restrict__ ed,
                                      int i, float4& acc) {
    int2 e0 = ed[i], e1 = ed[i + 1], e2 = ed[i + 2], e3 = ed[i + 3];
    uint2 q0 = *(const uint2*)(xl + (size_t)e0.x * 256);
    uint2 q1 = *(const uint2*)(xl + (size_t)e1.x * 256);
    uint2 q2 = *(const uint2*)(xl + (size_t)e2.x * 256);
    uint2 q3 = *(const uint2*)(xl + (size_t)e3.x * 256);
    accum4(acc, q0, __int_as_float(e0.y));
    accum4(acc, q1, __int_as_float(e1.y));
    accum4(acc, q2, __int_as_float(e2.y));
    accum4(acc, q3, __int_as_float(e3.y));
}

__device__ __forceinline__ void drain(const char* xl, const int2* __restrict__ ed,
                                      int i, int e, float4& acc) {
    for (; i + 4 <= e; i += 4) gath4(xl, ed, i, acc);
    for (; i < e; i++) {
        int2 e0 = ed[i];
        uint2 q = *(const uint2*)(xl + (size_t)e0.x * 256);
        accum4(acc, q, __int_as_float(e0.y));
    }
}

__device__ __forceinline__ void spmm_rowpair(const uint2* __restrict__ xh,
                                             const int* __restrict__ rp,
                                             const int2* __restrict__ ed,
                                             uint2* __restrict__ S, int row0, int lane) {
    const char* xl = (const char*)xh + (size_t)lane * 8;
    int s0 = rp[row0], m = rp[row0 + 1], e1 = rp[row0 + 2];
    float4 acc0 = make_float4(0.f, 0.f, 0.f, 0.f);
    float4 acc1 = make_float4(0.f, 0.f, 0.f, 0.f);
    int i0 = s0, i1 = m;
    // interleaved: two independent dependency chains, 8 gathers in flight
    while (i0 + 4 <= m && i1 + 4 <= e1) {
        gath4(xl, ed, i0, acc0);
        gath4(xl, ed, i1, acc1);
        i0 += 4; i1 += 4;
    }
    drain(xl, ed, i0, m,  acc0);
    drain(xl, ed, i1, e1, acc1);
    half2 a0 = __floats2half2_rn(acc0.x, acc0.y);
    half2 a1 = __floats2half2_rn(acc0.z, acc0.w);
    half2 b0 = __floats2half2_rn(acc1.x, acc1.y);
    half2 b1 = __floats2half2_rn(acc1.z, acc1.w);
    S[(size_t)row0 * 32 + lane]       = make_uint2(*(uint32_t*)&a0, *(uint32_t*)&a1);
    S[(size_t)(row0 + 1) * 32 + lane] = make_uint2(*(uint32_t*)&b0, *(uint32_t*)&b1);
}

__global__ __launch_bounds__(256, 4)
void spmm2_kernel() {
    int zb = blockIdx.x - SPBLK;
    if (zb >= 0) {                               // appended zero blocks (next-replay reset)
        int i = zb * 256 + threadIdx.x;
        if (i < NN0) g_fill0[i] = 0;
        else if (i < NN0 + NN2) g_fill2[i - NN0] = 0;
        else if (i < ZTOT) g_flagA[i - NN0 - NN2] = 0;
        return;
    }
    int warp = (blockIdx.x * 256 + threadIdx.x) >> 5;
    int lane = threadIdx.x & 31;
    if (warp < WPAIR0)                 spmm_rowpair(g_h0, g_rp0, g_e0, g_S0h, warp * 2, lane);
    else if (warp < WPAIR0 + WPAIR2)   spmm_rowpair(g_h1, g_rp2, g_e2, g_S2h,
                                                    (warp - WPAIR0) * 2, lane);
}

// ---------------- #5: persistent GEMM (R10-validated): resident W, cp.async A, ldmatrix ----------------
#define PADH 136
#define T0 ((NN0 + 63) / 64)
#define T2 ((NN2 + 63) / 64)
#define PB0 296
#define PB2 148
#define PBT (PB0 + PB2)              // 444 = 3 per SM
#define A_BUF (64 * PADH)
#define GSMEM ((DD * PADH + 2 * A_BUF) * 2)   // 69632 bytes

__device__ __forceinline__ void mma_f16(float* d, const uint32_t* a, const uint32_t* b) {
    asm volatile(
        "mma.sync.aligned.m16n8k16.row.col.f32.f16.f16.f32 "
        "{%0,%1,%2,%3}, {%4,%5,%6,%7}, {%8,%9}, {%0,%1,%2,%3};\n"
        : "+f"(d[0]), "+f"(d[1]), "+f"(d[2]), "+f"(d[3])
        : "r"(a[0]), "r"(a[1]), "r"(a[2]), "r"(a[3]), "r"(b[0]), "r"(b[1]));
}

__device__ __forceinline__ void ldsm_x4(uint32_t& r0, uint32_t& r1, uint32_t& r2,
                                        uint32_t& r3, uint32_t addr) {
    asm volatile("ldmatrix.sync.aligned.m8n8.x4.shared.b16 {%0,%1,%2,%3}, [%4];"
                 : "=r"(r0), "=r"(r1), "=r"(r2), "=r"(r3) : "r"(addr));
}

__device__ __forceinline__ void cp_async16(uint32_t dst_s, const void* src, int src_bytes) {
    asm volatile("cp.async.cg.shared.global [%0], [%1], 16, %2;"
                 :: "r"(dst_s), "l"(src), "r"(src_bytes));
}

__global__ __launch_bounds__(256, 3)
void gemm2_f16_relu_kernel(float* __restrict__ out_y0, float* __restrict__ out_y2) {
    const uint2* Sh; const __half* WT; float* out; int M, T, first, stride;
    if (blockIdx.x < PB0) {
        Sh = g_S0h; WT = g_WT0; out = out_y0; M = NN0;
        T = T0; first = blockIdx.x; stride = PB0;
    } else {
        Sh = g_S2h; WT = g_WT2; out = out_y2; M = NN2;
        T = T2; first = blockIdx.x - PB0; stride = PB2;
    }

    extern __shared__ __half hsm[];
    __half* sW = hsm;                    // [128][PADH]
    __half* sA = hsm + DD * PADH;        // [2][64][PADH]
    int tid = threadIdx.x;

    for (int idx = tid; idx < DD * 16; idx += 256) {
        int n = idx >> 4, kc = idx & 15;
        *(int4*)(sW + n * PADH + kc * 8) = ((const int4*)WT)[idx];
    }

    int lane = tid & 31, wid = tid >> 5;
    int g = lane >> 2, i4 = lane & 3;
    int mg = wid & 1, ng = wid >> 1;

    uint32_t sW_base = (uint32_t)__cvta_generic_to_shared(sW);
    uint32_t sA_base = (uint32_t)__cvta_generic_to_shared(sA);

    int j = lane >> 3, r8 = lane & 7;
    int mh = j & 1, khA = j >> 1;
    uint32_t aoff[2];
    #pragma unroll
    for (int mt = 0; mt < 2; mt++) {
        int row = mg * 32 + mt * 16 + mh * 8 + r8;
        aoff[mt] = row * (PADH * 2) + khA * 16;
    }
    int ntb = j >> 1, khB = j & 1;
    uint32_t boff0 = ((ng * 32 + ntb * 8 + r8) * PADH + khB * 8) * 2;
    uint32_t boff1 = boff0 + 16 * PADH * 2;

    int chunk_r[4], chunk_c[4];
    #pragma unroll
    for (int q = 0; q < 4; q++) {
        int idx = tid + q * 256;
        chunk_r[q] = idx >> 4;
        chunk_c[q] = idx & 15;
    }

    #define LOAD_TILE(buf, t) do {                                            \
        int m0_ = (t) * 64;                                                   \
        uint32_t dstb = sA_base + (buf) * (A_BUF * 2);                        \
        _Pragma("unroll")                                                     \
        for (int q = 0; q < 4; q++) {                                         \
            int gr = m0_ + chunk_r[q];                                        \
            uint32_t d = dstb + chunk_r[q] * (PADH * 2) + chunk_c[q] * 16;    \
            const char* s = (const char*)(Sh + (size_t)gr * 32) + chunk_c[q] * 16; \
            cp_async16(d, s, (gr < M) ? 16 : 0);                              \
        }                                                                     \
        asm volatile("cp.async.commit_group;");                               \
    } while (0)

    int t = first;
    if (t < T) LOAD_TILE(0, t);
    int buf = 0;
    __syncthreads();

    for (; t < T; t += stride) {
        int tn = t + stride;
        if (tn < T) {
            LOAD_TILE(buf ^ 1, tn);
            asm volatile("cp.async.wait_group 1;");
        } else {
            asm volatile("cp.async.wait_group 0;");
        }
        __syncthreads();

        uint32_t sAb = sA_base + buf * (A_BUF * 2);

        float acc[2][4][4];
        #pragma unroll
        for (int mt = 0; mt < 2; mt++)
            #pragma unroll
            for (int nt = 0; nt < 4; nt++)
                #pragma unroll
                for (int q = 0; q < 4; q++) acc[mt][nt][q] = 0.f;

        #pragma unroll
        for (int kk = 0; kk < 8; kk++) {
            uint32_t koff = kk * 32;
            uint32_t a[2][4], b[4][2];
            ldsm_x4(a[0][0], a[0][1], a[0][2], a[0][3], sAb + aoff[0] + koff);
            ldsm_x4(a[1][0], a[1][1], a[1][2], a[1][3], sAb + aoff[1] + koff);
            ldsm_x4(b[0][0], b[0][1], b[1][0], b[1][1], sW_base + boff0 + koff);
            ldsm_x4(b[2][0], b[2][1], b[3][0], b[3][1], sW_base + boff1 + koff);
            #pragma unroll
            for (int mt = 0; mt < 2; mt++)
                #pragma unroll
                for (int nt = 0; nt < 4; nt++)
                    mma_f16(acc[mt][nt], a[mt], b[nt]);
        }

        int m0 = t * 64;
        #pragma unroll
        for (int mt = 0; mt < 2; mt++) {
            int r0 = m0 + mg * 32 + mt * 16 + g;
            #pragma unroll
            for (int nt = 0; nt < 4; nt++) {
                int c = ng * 32 + nt * 8 + i4 * 2;
                if (r0 < M) {
                    float2 v = make_float2(fmaxf(acc[mt][nt][0], 0.f),
                                           fmaxf(acc[mt][nt][1], 0.f));
                    *(float2*)(out + (size_t)r0 * DD + c) = v;
                }
                if (r0 + 8 < M) {
                    float2 v = make_float2(fmaxf(acc[mt][nt][2], 0.f),
                                           fmaxf(acc[mt][nt][3], 0.f));
                    *(float2*)(out + (size_t)(r0 + 8) * DD + c) = v;
                }
            }
        }
        __syncthreads();
        buf ^= 1;
    }
    #undef LOAD_TILE
}

// ---------------- host launch ----------------
extern "C" void kernel_launch(void* const* d_in, const int* in_sizes, int n_in,
                              void* d_out, int out_size) {
    const float* x0  = (const float*)d_in[0];
    const float* x1  = (const float*)d_in[1];
    const int*   r00 = (const int*)  d_in[2];
    const int*   c00 = (const int*)  d_in[3];
    const float* v00 = (const float*)d_in[4];
    const int*   r12 = (const int*)  d_in[5];
    const int*   c12 = (const int*)  d_in[6];
    const float* v12 = (const float*)d_in[7];
    const float* W0  = (const float*)d_in[8];
    const float* W12 = (const float*)d_in[9];

    float* out    = (float*)d_out;
    float* out_y0 = out;
    float* out_x1 = out + (size_t)NN0 * DD;
    float* out_y2 = out + (size_t)(NN0 + NN1) * DD;

    hist2_kernel<<<(NNZ00 + NNZ12 + 255) / 256, 256>>>(r00, r12);          // #1
    convscan_kernel<<<NBT, 1024>>>(x0, x1, W0, W12, out_x1);               // #2
    fill2_kernel<<<(NNZ00 + NNZ12 + 255) / 256, 256>>>(r00, c00, v00,
                                                       r12, c12, v12);    // #3
    spmm2_kernel<<<SPBLK + ZBLK, 256>>>();                                 // #4 (profiled)
    cudaFuncSetAttribute(gemm2_f16_relu_kernel,
                         cudaFuncAttributeMaxDynamicSharedMemorySize, GSMEM);
    gemm2_f16_relu_kernel<<<PBT, 256, GSMEM>>>(out_y0, out_y2);            // #5
}

// round 16
// speedup vs baseline: 1.0065x; 1.0065x over previous
#include <cuda_runtime.h>
#include <cuda_fp16.h>
#include <math.h>
#include <stdint.h>

#define NN0 100000
#define NN1 150000
#define NN2 50000
#define NNZ00 1600000
#define NNZ12 200000
#define DD 128

#define NB0 98              // ceil(NN0/1024)
#define NB2 49              // ceil(NN2/1024)
#define NBT (NB0 + NB2)     // 147 <= 148 SMs: co-resident at occ 1

// ---------------- device scratch (zero-initialized; spmm zero-blocks restore) ----------------
__device__ uint2 g_h0[(size_t)NN0 * 32];       // relu(x0) fp16
__device__ uint2 g_h1[(size_t)NN1 * 32];       // relu(x1) fp16
__device__ uint2 g_S0h[(size_t)NN0 * 32];      // S0 fp16
__device__ uint2 g_S2h[(size_t)NN2 * 32];      // S2 fp16
__device__ __half g_WT0[DD * DD];              // W0^T fp16 [n][k]
__device__ __half g_WT2[DD * DD];              // W12^T fp16 [n][k]
__device__ __align__(16) int g_rp0[NN0 + 4];
__device__ __align__(16) int g_fill0[NN0];     // counts -> cursors (re-zeroed in spmm)
__device__ __align__(16) int g_rp2[NN2 + 4];
__device__ __align__(16) int g_fill2[NN2];
__device__ int  g_flagA[NBT];                  // lookback flags (re-zeroed in spmm)
__device__ __align__(16) int2 g_e0[NNZ00];
__device__ __align__(16) int2 g_e2[NNZ12];

// ---------------- #1: histogram ----------------
__global__ void hist2_kernel(const int* __restrict__ r00, const int* __restrict__ r12) {
    int i = blockIdx.x * blockDim.x + threadIdx.x;
    if (i < NNZ00) {
        atomicAdd(&g_fill0[r00[i]], 1);
    } else {
        int j = i - NNZ00;
        if (j < NNZ12) atomicAdd(&g_fill2[r12[j]], 1);
    }
}

// ---------------- #2: conversions + W transpose + out_x1 + decoupled-lookback scan ----------------
#define NAT (NBT * 1024)
__global__ __launch_bounds__(1024, 1)
void convscan_kernel(const float* __restrict__ x0, const float* __restrict__ x1,
                     const float* __restrict__ W0, const float* __restrict__ W12,
                     float* __restrict__ out_x1) {
    __shared__ int wsum[32];
    __shared__ int sh_agg;
    __shared__ int s_off;
    int tid  = threadIdx.x;
    int gtid = blockIdx.x * 1024 + tid;
    int b = blockIdx.x;

    int* cntfill; int* rp; int R; int base0; int lastcb;
    if (b < NB0) { cntfill = g_fill0; rp = g_rp0; R = NN0; base0 = 0;   lastcb = NB0 - 1; }
    else         { cntfill = g_fill2; rp = g_rp2; R = NN2; base0 = NB0; lastcb = NB2 - 1; }
    int cb  = b - base0;
    int idx = cb * 1024 + tid;

    // --- phase 1: block-local scan of counts + EARLY aggregate publish ---
    int c = (idx < R) ? cntfill[idx] : 0;
    int lane = tid & 31, w = tid >> 5;
    int inc = c;
    #pragma unroll
    for (int off = 1; off < 32; off <<= 1) {
        int v = __shfl_up_sync(0xffffffffu, inc, off);
        if (lane >= off) inc += v;
    }
    if (lane == 31) wsum[w] = inc;
    if (tid == 0) s_off = 0;
    __syncthreads();
    if (w == 0) {
        int v = wsum[lane];
        int winc = v;
        #pragma unroll
        for (int off = 1; off < 32; off <<= 1) {
            int u = __shfl_up_sync(0xffffffffu, winc, off);
            if (lane >= off) winc += u;
        }
        wsum[lane] = winc - v;
        if (lane == 31) {
            sh_agg = winc;
            atomicExch(&g_flagA[b], winc + 1);
        }
    }
    __syncthreads();

    // --- phase 2: bulk conversions (streaming hints on single-use data) ---
    for (int i = gtid; i < DD * DD; i += NAT) {
        int r = i >> 7, cc = i & 127;
        g_WT0[cc * DD + r] = __float2half_rn(W0[i]);
        g_WT2[cc * DD + r] = __float2half_rn(W12[i]);
    }
    for (int i = gtid; i < NN0 * 32; i += NAT) {
        float4 v = __ldcs((const float4*)x0 + i);
        half2 p0 = __floats2half2_rn(fmaxf(v.x, 0.f), fmaxf(v.y, 0.f));
        half2 p1 = __floats2half2_rn(fmaxf(v.z, 0.f), fmaxf(v.w, 0.f));
        g_h0[i] = make_uint2(*(uint32_t*)&p0, *(uint32_t*)&p1);
    }
    for (int i = gtid; i < NN1 * 32; i += NAT) {
        float4 v = __ldcs((const float4*)x1 + i);
        v.x = fmaxf(v.x, 0.f); v.y = fmaxf(v.y, 0.f);
        v.z = fmaxf(v.z, 0.f); v.w = fmaxf(v.w, 0.f);
        __stcs((float4*)out_x1 + i, v);
        half2 p0 = __floats2half2_rn(v.x, v.y);
        half2 p1 = __floats2half2_rn(v.z, v.w);
        g_h1[i] = make_uint2(*(uint32_t*)&p0, *(uint32_t*)&p1);
    }

    // --- phase 3: lookback (flags long published) ---
    int local = 0;
    for (int j = base0 + tid; j < b; j += 1024) {
        int v;
        while ((v = *(volatile int*)&g_flagA[j]) == 0) __nanosleep(20);
        local += v - 1;
    }
    if (local) atomicAdd(&s_off, local);
    __syncthreads();
    int off = s_off;

    if (idx < R) {
        int v = off + wsum[w] + inc - c;
        rp[idx]      = v;
        cntfill[idx] = v;
    }
    if (tid == 0 && cb == lastcb) rp[R] = off + sh_agg;
}

// ---------------- #3: CSR fill ----------------
__global__ void fill2_kernel(const int* __restrict__ r00, const int* __restrict__ c00,
                             const float* __restrict__ v00,
                             const int* __restrict__ r12, const int* __restrict__ c12,
                             const float* __restrict__ v12) {
    int i = blockIdx.x * blockDim.x + threadIdx.x;
    if (i < NNZ00) {
        int p = atomicAdd(&g_fill0[r00[i]], 1);
        g_e0[p] = make_int2(c00[i], __float_as_int(v00[i]));
    } else {
        int j = i - NNZ00;
        if (j < NNZ12) {
            int p = atomicAdd(&g_fill2[r12[j]], 1);
            g_e2[p] = make_int2(c12[j], __float_as_int(v12[j]));
        }
    }
}

// ---------------- #4: SpMM (two interleaved rows per warp, R15-measured 68us) ----------------
#define WPAIR0 (NN0 / 2)
#define WPAIR2 (NN2 / 2)
#define SPBLK ((WPAIR0 + WPAIR2) * 32 / 256)   // 9375 compute blocks
#define ZTOT  (NN0 + NN2 + NBT)
#define ZBLK  ((ZTOT + 255) / 256)

__device__ __forceinline__ void accum4(float4& acc, uint2 q, float v) {
    float2 f0 = __half22float2(*(half2*)&q.x);
    float2 f1 = __half22float2(*(half2*)&q.y);
    acc.x = fmaf(v, f0.x, acc.x);
    acc.y = fmaf(v, f0.y, acc.y);
    acc.z = fmaf(v, f1.x, acc.z);
    acc.w = fmaf(v, f1.y, acc.w);
}

__device__ __forceinline__ void gath4(const char* xl, const int2* __restrict__ ed,
                                      int i, float4& acc) {
    int2 e0 = ed[i], e1 = ed[i + 1], e2 = ed[i + 2], e3 = ed[i + 3];
    uint2 q0 = *(const uint2*)(xl + (size_t)e0.x * 256);
    uint2 q1 = *(const uint2*)(xl + (size_t)e1.x * 256);
    uint2 q2 = *(const uint2*)(xl + (size_t)e2.x * 256);
    uint2 q3 = *(const uint2*)(xl + (size_t)e3.x * 256);
    accum4(acc, q0, __int_as_float(e0.y));
    accum4(acc, q1, __int_as_float(e1.y));
    accum4(acc, q2, __int_as_float(e2.y));
    accum4(acc, q3, __int_as_float(e3.y));
}

__device__ __forceinline__ void drain(const char* xl, const int2* __restrict__ ed,
                                      int i, int e, float4& acc) {
    for (; i + 4 <= e; i += 4) gath4(xl, ed, i, acc);
    for (; i < e; i++) {
        int2 e0 = ed[i];
        uint2 q = *(const uint2*)(xl + (size_t)e0.x * 256);
        accum4(acc, q, __int_as_float(e0.y));
    }
}

__device__ __forceinline__ void spmm_rowpair(const uint2* __restrict__ xh,
                                             const int* __restrict__ rp,
                                             const int2* __restrict__ ed,
                                             uint2* __restrict__ S, int row0, int lane) {
    const char* xl = (const char*)xh + (size_t)lane * 8;
    int s0 = rp[row0], m = rp[row0 + 1], e1 = rp[row0 + 2];
    float4 acc0 = make_float4(0.f, 0.f, 0.f, 0.f);
    float4 acc1 = make_float4(0.f, 0.f, 0.f, 0.f);
    int i0 = s0, i1 = m;
    while (i0 + 4 <= m && i1 + 4 <= e1) {
        gath4(xl, ed, i0, acc0);
        gath4(xl, ed, i1, acc1);
        i0 += 4; i1 += 4;
    }
    drain(xl, ed, i0, m,  acc0);
    drain(xl, ed, i1, e1, acc1);
    half2 a0 = __floats2half2_rn(acc0.x, acc0.y);
    half2 a1 = __floats2half2_rn(acc0.z, acc0.w);
    half2 b0 = __floats2half2_rn(acc1.x, acc1.y);
    half2 b1 = __floats2half2_rn(acc1.z, acc1.w);
    S[(size_t)row0 * 32 + lane]       = make_uint2(*(uint32_t*)&a0, *(uint32_t*)&a1);
    S[(size_t)(row0 + 1) * 32 + lane] = make_uint2(*(uint32_t*)&b0, *(uint32_t*)&b1);
}

__global__ __launch_bounds__(256, 4)
void spmm2_kernel() {
    int zb = blockIdx.x - SPBLK;
    if (zb >= 0) {                               // appended zero blocks (next-replay reset)
        int i = zb * 256 + threadIdx.x;
        if (i < NN0) g_fill0[i] = 0;
        else if (i < NN0 + NN2) g_fill2[i - NN0] = 0;
        else if (i < ZTOT) g_flagA[i - NN0 - NN2] = 0;
        return;
    }
    int warp = (blockIdx.x * 256 + threadIdx.x) >> 5;
    int lane = threadIdx.x & 31;
    if (warp < WPAIR0)                 spmm_rowpair(g_h0, g_rp0, g_e0, g_S0h, warp * 2, lane);
    else if (warp < WPAIR0 + WPAIR2)   spmm_rowpair(g_h1, g_rp2, g_e2, g_S2h,
                                                    (warp - WPAIR0) * 2, lane);
}

// ---------------- #5: barrier-free warp-stream GEMM ----------------
// Each warp owns 16-row x 128-col output tiles, private double-buffered smem A
// slice, per-warp cp.async pipeline. No block barriers after W staging.
#define PADH 136
#define ROWB (PADH * 2)              // 272 bytes per A row
#define ABUFB (16 * ROWB)            // 4352 bytes per A buffer
#define T16_0 (NN0 / 16)             // 6250 (exact)
#define T16_2 (NN2 / 16)             // 3125 (exact)
#define PB0 197
#define PB2 99
#define PBT (PB0 + PB2)              // 296 = 2 per SM
#define GSMEM (DD * ROWB + 8 * 2 * ABUFB)   // 34816 + 69632 = 104448 bytes

__device__ __forceinline__ void mma_f16(float* d, const uint32_t* a, const uint32_t* b) {
    asm volatile(
        "mma.sync.aligned.m16n8k16.row.col.f32.f16.f16.f32 "
        "{%0,%1,%2,%3}, {%4,%5,%6,%7}, {%8,%9}, {%0,%1,%2,%3};\n"
        : "+f"(d[0]), "+f"(d[1]), "+f"(d[2]), "+f"(d[3])
        : "r"(a[0]), "r"(a[1]), "r"(a[2]), "r"(a[3]), "r"(b[0]), "r"(b[1]));
}

__device__ __forceinline__ void ldsm_x4(uint32_t& r0, uint32_t& r1, uint32_t& r2,
                                        uint32_t& r3, uint32_t addr) {
    asm volatile("ldmatrix.sync.aligned.m8n8.x4.shared.b16 {%0,%1,%2,%3}, [%4];"
                 : "=r"(r0), "=r"(r1), "=r"(r2), "=r"(r3) : "r"(addr));
}

__device__ __forceinline__ void cp_async16(uint32_t dst_s, const void* src) {
    asm volatile("cp.async.cg.shared.global [%0], [%1], 16;"
                 :: "r"(dst_s), "l"(src));
}

__global__ __launch_bounds__(256, 2)
void gemm3_f16_relu_kernel(float* __restrict__ out_y0, float* __restrict__ out_y2) {
    const uint2* Sh; const __half* WT; float* out; int T, first_b;
    if (blockIdx.x < PB0) {
        Sh = g_S0h; WT = g_WT0; out = out_y0; T = T16_0; first_b = blockIdx.x;
    } else {
        Sh = g_S2h; WT = g_WT2; out = out_y2; T = T16_2; first_b = blockIdx.x - PB0;
    }
    int wstride = (blockIdx.x < PB0) ? PB0 * 8 : PB2 * 8;

    extern __shared__ __half hsm[];
    __half* sW = hsm;                        // [128][PADH]
    int tid = threadIdx.x;
    int lane = tid & 31, wid = tid >> 5;

    // stage W plane once (block-cooperative)
    for (int idx = tid; idx < DD * 16; idx += 256) {
        int n = idx >> 4, kc = idx & 15;
        *(int4*)(sW + n * PADH + kc * 8) = ((const int4*)WT)[idx];
    }

    uint32_t sW_base  = (uint32_t)__cvta_generic_to_shared(sW);
    uint32_t sAw_base = (uint32_t)__cvta_generic_to_shared(hsm + DD * PADH)
                        + wid * (2 * ABUFB);

    // ldmatrix lane addressing (validated mapping from R10 kernel)
    int j = lane >> 3, r8 = lane & 7;
    int mh = j & 1, khA = j >> 1;
    uint32_t aoff = (mh * 8 + r8) * ROWB + khA * 16;
    int ntb = j >> 1, khB = j & 1;
    uint32_t boff = (ntb * 8 + r8) * ROWB + khB * 16;   // + p*16*ROWB per n-pair

    int g = lane >> 2, i4 = lane & 3;

    #define LOAD16(buf, t) do {                                               \
        uint32_t dstb = sAw_base + (buf) * ABUFB;                             \
        const char* srcb = (const char*)Sh + (size_t)(t) * 16 * 256;          \
        _Pragma("unroll")                                                     \
        for (int q = 0; q < 8; q++) {                                         \
            int idx = lane + q * 32;                                          \
            int rr = idx >> 4, cc = idx & 15;                                 \
            cp_async16(dstb + rr * ROWB + cc * 16, srcb + rr * 256 + cc * 16);\
        }                                                                     \
        asm volatile("cp.async.commit_group;");                               \
    } while (0)

    int t = first_b * 8 + wid;
    if (t < T) LOAD16(0, t);
    int buf = 0;
    __syncthreads();          // W plane ready

    for (; t < T; t += wstride) {
        int tn = t + wstride;
        if (tn < T) {
            LOAD16(buf ^ 1, tn);
            asm volatile("cp.async.wait_group 1;");
        } else {
            asm volatile("cp.async.wait_group 0;");
        }
        __syncwarp();

        uint32_t sAb = sAw_base + buf * ABUFB;

        float acc[16][4];
        #pragma unroll
        for (int nt = 0; nt < 16; nt++)
            #pragma unroll
            for (int q = 0; q < 4; q++) acc[nt][q] = 0.f;

        #pragma unroll
        for (int kk = 0; kk < 8; kk++) {
            uint32_t koff = kk * 32;
            uint32_t a[4];
            ldsm_x4(a[0], a[1], a[2], a[3], sAb + aoff + koff);
            #pragma unroll
            for (int p = 0; p < 8; p++) {
                uint32_t b[4];
                ldsm_x4(b[0], b[1], b[2], b[3],
                        sW_base + boff + p * (16 * ROWB) + koff);
                mma_f16(acc[2 * p],     a, b);
                mma_f16(acc[2 * p + 1], a, b + 2);
            }
        }

        int m0 = t * 16;
        int r0 = m0 + g, r1 = m0 + 8 + g;     // exact tiles: no bounds checks
        #pragma unroll
        for (int nt = 0; nt < 16; nt++) {
            int c = nt * 8 + i4 * 2;
            float2 v0 = make_float2(fmaxf(acc[nt][0], 0.f), fmaxf(acc[nt][1], 0.f));
            float2 v1 = make_float2(fmaxf(acc[nt][2], 0.f), fmaxf(acc[nt][3], 0.f));
            *(float2*)(out + (size_t)r0 * DD + c) = v0;
            *(float2*)(out + (size_t)r1 * DD + c) = v1;
        }
        __syncwarp();        // all lanes done reading buf before next overwrite
        buf ^= 1;
    }
    #undef LOAD16
}

// ---------------- host launch ----------------
extern "C" void kernel_launch(void* const* d_in, const int* in_sizes, int n_in,
                              void* d_out, int out_size) {
    const float* x0  = (const float*)d_in[0];
    const float* x1  = (const float*)d_in[1];
    const int*   r00 = (const int*)  d_in[2];
    const int*   c00 = (const int*)  d_in[3];
    const float* v00 = (const float*)d_in[4];
    const int*   r12 = (const int*)  d_in[5];
    const int*   c12 = (const int*)  d_in[6];
    const float* v12 = (const float*)d_in[7];
    const float* W0  = (const float*)d_in[8];
    const float* W12 = (const float*)d_in[9];

    float* out    = (float*)d_out;
    float* out_y0 = out;
    float* out_x1 = out + (size_t)NN0 * DD;
    float* out_y2 = out + (size_t)(NN0 + NN1) * DD;

    hist2_kernel<<<(NNZ00 + NNZ12 + 255) / 256, 256>>>(r00, r12);          // #1
    convscan_kernel<<<NBT, 1024>>>(x0, x1, W0, W12, out_x1);               // #2
    fill2_kernel<<<(NNZ00 + NNZ12 + 255) / 256, 256>>>(r00, c00, v00,
                                                       r12, c12, v12);    // #3
    spmm2_kernel<<<SPBLK + ZBLK, 256>>>();                                 // #4 (profiled)
    cudaFuncSetAttribute(gemm3_f16_relu_kernel,
                         cudaFuncAttributeMaxDynamicSharedMemorySize, GSMEM);
    gemm3_f16_relu_kernel<<<PBT, 256, GSMEM>>>(out_y0, out_y2);            // #5
}

// round 17
// speedup vs baseline: 1.1135x; 1.1063x over previous
#include <cuda_runtime.h>
#include <cuda_fp16.h>
#include <math.h>
#include <stdint.h>

#define NN0 100000
#define NN1 150000
#define NN2 50000
#define NNZ00 1600000
#define NNZ12 200000
#define DD 128

#define NB0 98              // ceil(NN0/1024)
#define NB2 49              // ceil(NN2/1024)
#define NBT (NB0 + NB2)     // 147 scan blocks

// ---------------- device scratch (zero-initialized; spmm zero-blocks restore) ----------------
__device__ uint2 g_h0[(size_t)NN0 * 32];       // relu(x0) fp16
__device__ uint2 g_h1[(size_t)NN1 * 32];       // relu(x1) fp16
__device__ uint2 g_S0h[(size_t)NN0 * 32];      // S0 fp16
__device__ uint2 g_S2h[(size_t)NN2 * 32];      // S2 fp16
__device__ __half g_WT0[DD * DD];              // W0^T fp16 [n][k]
__device__ __half g_WT2[DD * DD];              // W12^T fp16 [n][k]
__device__ __align__(16) int g_rp0[NN0 + 4];
__device__ __align__(16) int g_fill0[NN0];     // counts -> cursors (re-zeroed in spmm)
__device__ __align__(16) int g_rp2[NN2 + 4];
__device__ __align__(16) int g_fill2[NN2];
__device__ int  g_flagA[NBT];                  // lookback flags (re-zeroed in spmm)
__device__ __align__(16) int2 g_e0[NNZ00];
__device__ __align__(16) int2 g_e2[NNZ12];

// ---------------- edge path A: histogram ----------------
__global__ void hist2_kernel(const int* __restrict__ r00, const int* __restrict__ r12) {
    int i = blockIdx.x * blockDim.x + threadIdx.x;
    if (i < NNZ00) {
        atomicAdd(&g_fill0[r00[i]], 1);
    } else {
        int j = i - NNZ00;
        if (j < NNZ12) atomicAdd(&g_fill2[r12[j]], 1);
    }
}

// ---------------- edge path B: decoupled-lookback scan (any-residency safe) ----------------
__global__ __launch_bounds__(1024, 1)
void scan_kernel() {
    __shared__ int wsum[32];
    __shared__ int sh_agg;
    __shared__ int s_off;
    int tid = threadIdx.x;
    int b = blockIdx.x;

    int* cntfill; int* rp; int R; int base0; int lastcb;
    if (b < NB0) { cntfill = g_fill0; rp = g_rp0; R = NN0; base0 = 0;   lastcb = NB0 - 1; }
    else         { cntfill = g_fill2; rp = g_rp2; R = NN2; base0 = NB0; lastcb = NB2 - 1; }
    int cb  = b - base0;
    int idx = cb * 1024 + tid;

    int c = (idx < R) ? cntfill[idx] : 0;
    int lane = tid & 31, w = tid >> 5;
    int inc = c;
    #pragma unroll
    for (int off = 1; off < 32; off <<= 1) {
        int v = __shfl_up_sync(0xffffffffu, inc, off);
        if (lane >= off) inc += v;
    }
    if (lane == 31) wsum[w] = inc;
    if (tid == 0) s_off = 0;
    __syncthreads();
    if (w == 0) {
        int v = wsum[lane];
        int winc = v;
        #pragma unroll
        for (int off = 1; off < 32; off <<= 1) {
            int u = __shfl_up_sync(0xffffffffu, winc, off);
            if (lane >= off) winc += u;
        }
        wsum[lane] = winc - v;
        if (lane == 31) {
            sh_agg = winc;
            atomicExch(&g_flagA[b], winc + 1);      // publish aggregate
        }
    }
    __syncthreads();

    // lookback: predecessors have lower bid -> scheduled earlier -> no deadlock
    int local = 0;
    for (int j = base0 + tid; j < b; j += 1024) {
        int v;
        while ((v = *(volatile int*)&g_flagA[j]) == 0) __nanosleep(20);
        local += v - 1;
    }
    if (local) atomicAdd(&s_off, local);
    __syncthreads();
    int off = s_off;

    if (idx < R) {
        int v = off + wsum[w] + inc - c;
        rp[idx]      = v;
        cntfill[idx] = v;                           // fill cursor
    }
    if (tid == 0 && cb == lastcb) rp[R] = off + sh_agg;
}

// ---------------- dense path (side stream): conversions + W transpose + out_x1 ----------------
#define CBLK 1024
#define CTHR (CBLK * 256)
__global__ __launch_bounds__(256)
void conv_kernel(const float* __restrict__ x0, const float* __restrict__ x1,
                 const float* __restrict__ W0, const float* __restrict__ W12,
                 float* __restrict__ out_x1) {
    int gtid = blockIdx.x * 256 + threadIdx.x;

    for (int i = gtid; i < DD * DD; i += CTHR) {
        int r = i >> 7, cc = i & 127;
        g_WT0[cc * DD + r] = __float2half_rn(W0[i]);
        g_WT2[cc * DD + r] = __float2half_rn(W12[i]);
    }
    for (int i = gtid; i < NN0 * 32; i += CTHR) {
        float4 v = __ldcs((const float4*)x0 + i);
        half2 p0 = __floats2half2_rn(fmaxf(v.x, 0.f), fmaxf(v.y, 0.f));
        half2 p1 = __floats2half2_rn(fmaxf(v.z, 0.f), fmaxf(v.w, 0.f));
        g_h0[i] = make_uint2(*(uint32_t*)&p0, *(uint32_t*)&p1);
    }
    for (int i = gtid; i < NN1 * 32; i += CTHR) {
        float4 v = __ldcs((const float4*)x1 + i);
        v.x = fmaxf(v.x, 0.f); v.y = fmaxf(v.y, 0.f);
        v.z = fmaxf(v.z, 0.f); v.w = fmaxf(v.w, 0.f);
        __stcs((float4*)out_x1 + i, v);
        half2 p0 = __floats2half2_rn(v.x, v.y);
        half2 p1 = __floats2half2_rn(v.z, v.w);
        g_h1[i] = make_uint2(*(uint32_t*)&p0, *(uint32_t*)&p1);
    }
}

// ---------------- edge path C: CSR fill (profiled slot #4) ----------------
__global__ void fill2_kernel(const int* __restrict__ r00, const int* __restrict__ c00,
                             const float* __restrict__ v00,
                             const int* __restrict__ r12, const int* __restrict__ c12,
                             const float* __restrict__ v12) {
    int i = blockIdx.x * blockDim.x + threadIdx.x;
    if (i < NNZ00) {
        int p = atomicAdd(&g_fill0[r00[i]], 1);
        g_e0[p] = make_int2(c00[i], __float_as_int(v00[i]));
    } else {
        int j = i - NNZ00;
        if (j < NNZ12) {
            int p = atomicAdd(&g_fill2[r12[j]], 1);
            g_e2[p] = make_int2(c12[j], __float_as_int(v12[j]));
        }
    }
}

// ---------------- SpMM: two interleaved rows per warp (R15-measured 68us) ----------------
#define WPAIR0 (NN0 / 2)
#define WPAIR2 (NN2 / 2)
#define SPBLK ((WPAIR0 + WPAIR2) * 32 / 256)   // 9375 compute blocks
#define ZTOT  (NN0 + NN2 + NBT)
#define ZBLK  ((ZTOT + 255) / 256)

__device__ __forceinline__ void accum4(float4& acc, uint2 q, float v) {
    float2 f0 = __half22float2(*(half2*)&q.x);
    float2 f1 = __half22float2(*(half2*)&q.y);
    acc.x = fmaf(v, f0.x, acc.x);
    acc.y = fmaf(v, f0.y, acc.y);
    acc.z = fmaf(v, f1.x, acc.z);
    acc.w = fmaf(v, f1.y, acc.w);
}

__device__ __forceinline__ void gath4(const char* xl, const int2* __restrict__ ed,
                                      int i, float4& acc) {
    int2 e0 = ed[i], e1 = ed[i + 1], e2 = ed[i + 2], e3 = ed[i + 3];
    uint2 q0 = *(const uint2*)(xl + (size_t)e0.x * 256);
    uint2 q1 = *(const uint2*)(xl + (size_t)e1.x * 256);
    uint2 q2 = *(const uint2*)(xl + (size_t)e2.x * 256);
    uint2 q3 = *(const uint2*)(xl + (size_t)e3.x * 256);
    accum4(acc, q0, __int_as_float(e0.y));
    accum4(acc, q1, __int_as_float(e1.y));
    accum4(acc, q2, __int_as_float(e2.y));
    accum4(acc, q3, __int_as_float(e3.y));
}

__device__ __forceinline__ void drain(const char* xl, const int2* __restrict__ ed,
                                      int i, int e, float4& acc) {
    for (; i + 4 <= e; i += 4) gath4(xl, ed, i, acc);
    for (; i < e; i++) {
        int2 e0 = ed[i];
        uint2 q = *(const uint2*)(xl + (size_t)e0.x * 256);
        accum4(acc, q, __int_as_float(e0.y));
    }
}

__device__ __forceinline__ void spmm_rowpair(const uint2* __restrict__ xh,
                                             const int* __restrict__ rp,
                                             const int2* __restrict__ ed,
                                             uint2* __restrict__ S, int row0, int lane) {
    const char* xl = (const char*)xh + (size_t)lane * 8;
    int s0 = rp[row0], m = rp[row0 + 1], e1 = rp[row0 + 2];
    float4 acc0 = make_float4(0.f, 0.f, 0.f, 0.f);
    float4 acc1 = make_float4(0.f, 0.f, 0.f, 0.f);
    int i0 = s0, i1 = m;
    while (i0 + 4 <= m && i1 + 4 <= e1) {
        gath4(xl, ed, i0, acc0);
        gath4(xl, ed, i1, acc1);
        i0 += 4; i1 += 4;
    }
    drain(xl, ed, i0, m,  acc0);
    drain(xl, ed, i1, e1, acc1);
    half2 a0 = __floats2half2_rn(acc0.x, acc0.y);
    half2 a1 = __floats2half2_rn(acc0.z, acc0.w);
    half2 b0 = __floats2half2_rn(acc1.x, acc1.y);
    half2 b1 = __floats2half2_rn(acc1.z, acc1.w);
    S[(size_t)row0 * 32 + lane]       = make_uint2(*(uint32_t*)&a0, *(uint32_t*)&a1);
    S[(size_t)(row0 + 1) * 32 + lane] = make_uint2(*(uint32_t*)&b0, *(uint32_t*)&b1);
}

__global__ __launch_bounds__(256, 4)
void spmm2_kernel() {
    int zb = blockIdx.x - SPBLK;
    if (zb >= 0) {                               // appended zero blocks (next-replay reset)
        int i = zb * 256 + threadIdx.x;
        if (i < NN0) g_fill0[i] = 0;
        else if (i < NN0 + NN2) g_fill2[i - NN0] = 0;
        else if (i < ZTOT) g_flagA[i - NN0 - NN2] = 0;
        return;
    }
    int warp = (blockIdx.x * 256 + threadIdx.x) >> 5;
    int lane = threadIdx.x & 31;
    if (warp < WPAIR0)                 spmm_rowpair(g_h0, g_rp0, g_e0, g_S0h, warp * 2, lane);
    else if (warp < WPAIR0 + WPAIR2)   spmm_rowpair(g_h1, g_rp2, g_e2, g_S2h,
                                                    (warp - WPAIR0) * 2, lane);
}

// ---------------- barrier-free warp-stream GEMM (R16) ----------------
#define PADH 136
#define ROWB (PADH * 2)
#define ABUFB (16 * ROWB)
#define T16_0 (NN0 / 16)
#define T16_2 (NN2 / 16)
#define PB0 197
#define PB2 99
#define PBT (PB0 + PB2)
#define GSMEM (DD * ROWB + 8 * 2 * ABUFB)   // 104448 bytes

__device__ __forceinline__ void mma_f16(float* d, const uint32_t* a, const uint32_t* b) {
    asm volatile(
        "mma.sync.aligned.m16n8k16.row.col.f32.f16.f16.f32 "
        "{%0,%1,%2,%3}, {%4,%5,%6,%7}, {%8,%9}, {%0,%1,%2,%3};\n"
        : "+f"(d[0]), "+f"(d[1]), "+f"(d[2]), "+f"(d[3])
        : "r"(a[0]), "r"(a[1]), "r"(a[2]), "r"(a[3]), "r"(b[0]), "r"(b[1]));
}

__device__ __forceinline__ void ldsm_x4(uint32_t& r0, uint32_t& r1, uint32_t& r2,
                                        uint32_t& r3, uint32_t addr) {
    asm volatile("ldmatrix.sync.aligned.m8n8.x4.shared.b16 {%0,%1,%2,%3}, [%4];"
                 : "=r"(r0), "=r"(r1), "=r"(r2), "=r"(r3) : "r"(addr));
}

__device__ __forceinline__ void cp_async16(uint32_t dst_s, const void* src) {
    asm volatile("cp.async.cg.shared.global [%0], [%1], 16;"
                 :: "r"(dst_s), "l"(src));
}

__global__ __launch_bounds__(256, 2)
void gemm3_f16_relu_kernel(float* __restrict__ out_y0, float* __restrict__ out_y2) {
    const uint2* Sh; const __half* WT; float* out; int T, first_b;
    if (blockIdx.x < PB0) {
        Sh = g_S0h; WT = g_WT0; out = out_y0; T = T16_0; first_b = blockIdx.x;
    } else {
        Sh = g_S2h; WT = g_WT2; out = out_y2; T = T16_2; first_b = blockIdx.x - PB0;
    }
    int wstride = (blockIdx.x < PB0) ? PB0 * 8 : PB2 * 8;

    extern __shared__ __half hsm[];
    __half* sW = hsm;
    int tid = threadIdx.x;
    int lane = tid & 31, wid = tid >> 5;

    for (int idx = tid; idx < DD * 16; idx += 256) {
        int n = idx >> 4, kc = idx & 15;
        *(int4*)(sW + n * PADH + kc * 8) = ((const int4*)WT)[idx];
    }

    uint32_t sW_base  = (uint32_t)__cvta_generic_to_shared(sW);
    uint32_t sAw_base = (uint32_t)__cvta_generic_to_shared(hsm + DD * PADH)
                        + wid * (2 * ABUFB);

    int j = lane >> 3, r8 = lane & 7;
    int mh = j & 1, khA = j >> 1;
    uint32_t aoff = (mh * 8 + r8) * ROWB + khA * 16;
    int ntb = j >> 1, khB = j & 1;
    uint32_t boff = (ntb * 8 + r8) * ROWB + khB * 16;

    int g = lane >> 2, i4 = lane & 3;

    #define LOAD16(buf, t) do {                                               \
        uint32_t dstb = sAw_base + (buf) * ABUFB;                             \
        const char* srcb = (const char*)Sh + (size_t)(t) * 16 * 256;          \
        _Pragma("unroll")                                                     \
        for (int q = 0; q < 8; q++) {                                         \
            int idx = lane + q * 32;                                          \
            int rr = idx >> 4, cc = idx & 15;                                 \
            cp_async16(dstb + rr * ROWB + cc * 16, srcb + rr * 256 + cc * 16);\
        }                                                                     \
        asm volatile("cp.async.commit_group;");                               \
    } while (0)

    int t = first_b * 8 + wid;
    if (t < T) LOAD16(0, t);
    int buf = 0;
    __syncthreads();

    for (; t < T; t += wstride) {
        int tn = t + wstride;
        if (tn < T) {
            LOAD16(buf ^ 1, tn);
            asm volatile("cp.async.wait_group 1;");
        } else {
            asm volatile("cp.async.wait_group 0;");
        }
        __syncwarp();

        uint32_t sAb = sAw_base + buf * ABUFB;

        float acc[16][4];
        #pragma unroll
        for (int nt = 0; nt < 16; nt++)
            #pragma unroll
            for (int q = 0; q < 4; q++) acc[nt][q] = 0.f;

        #pragma unroll
        for (int kk = 0; kk < 8; kk++) {
            uint32_t koff = kk * 32;
            uint32_t a[4];
            ldsm_x4(a[0], a[1], a[2], a[3], sAb + aoff + koff);
            #pragma unroll
            for (int p = 0; p < 8; p++) {
                uint32_t b[4];
                ldsm_x4(b[0], b[1], b[2], b[3],
                        sW_base + boff + p * (16 * ROWB) + koff);
                mma_f16(acc[2 * p],     a, b);
                mma_f16(acc[2 * p + 1], a, b + 2);
            }
        }

        int m0 = t * 16;
        int r0 = m0 + g, r1 = m0 + 8 + g;
        #pragma unroll
        for (int nt = 0; nt < 16; nt++) {
            int c = nt * 8 + i4 * 2;
            float2 v0 = make_float2(fmaxf(acc[nt][0], 0.f), fmaxf(acc[nt][1], 0.f));
            float2 v1 = make_float2(fmaxf(acc[nt][2], 0.f), fmaxf(acc[nt][3], 0.f));
            *(float2*)(out + (size_t)r0 * DD + c) = v0;
            *(float2*)(out + (size_t)r1 * DD + c) = v1;
        }
        __syncwarp();
        buf ^= 1;
    }
    #undef LOAD16
}

// ---------------- host launch: fork-join two-stream graph ----------------
extern "C" void kernel_launch(void* const* d_in, const int* in_sizes, int n_in,
                              void* d_out, int out_size) {
    const float* x0  = (const float*)d_in[0];
    const float* x1  = (const float*)d_in[1];
    const int*   r00 = (const int*)  d_in[2];
    const int*   c00 = (const int*)  d_in[3];
    const float* v00 = (const float*)d_in[4];
    const int*   r12 = (const int*)  d_in[5];
    const int*   c12 = (const int*)  d_in[6];
    const float* v12 = (const float*)d_in[7];
    const float* W0  = (const float*)d_in[8];
    const float* W12 = (const float*)d_in[9];

    float* out    = (float*)d_out;
    float* out_y0 = out;
    float* out_x1 = out + (size_t)NN0 * DD;
    float* out_y2 = out + (size_t)(NN0 + NN1) * DD;

    // one-time host-object init (no device memory; identical captured work per call)
    static cudaStream_t s_side = nullptr;
    static cudaEvent_t  s_fork = nullptr, s_join = nullptr;
    if (s_side == nullptr) {
        cudaStreamCreateWithFlags(&s_side, cudaStreamNonBlocking);
        cudaEventCreateWithFlags(&s_fork, cudaEventDisableTiming);
        cudaEventCreateWithFlags(&s_join, cudaEventDisableTiming);
    }

    // fork: dense path on side stream
    cudaEventRecord(s_fork, 0);
    cudaStreamWaitEvent(s_side, s_fork, 0);
    conv_kernel<<<CBLK, 256, 0, s_side>>>(x0, x1, W0, W12, out_x1);        // #2 (side)
    cudaEventRecord(s_join, s_side);

    // edge path on main stream (concurrent with conv)
    hist2_kernel<<<(NNZ00 + NNZ12 + 255) / 256, 256>>>(r00, r12);          // #1
    scan_kernel<<<NBT, 1024>>>();                                          // #3
    fill2_kernel<<<(NNZ00 + NNZ12 + 255) / 256, 256>>>(r00, c00, v00,
                                                       r12, c12, v12);    // #4 (profiled)

    // join: spmm needs CSR + h0/h1
    cudaStreamWaitEvent(0, s_join, 0);
    spmm2_kernel<<<SPBLK + ZBLK, 256>>>();                                 // #5
    cudaFuncSetAttribute(gemm3_f16_relu_kernel,
                         cudaFuncAttributeMaxDynamicSharedMemorySize, GSMEM);
    gemm3_f16_relu_kernel<<<PBT, 256, GSMEM>>>(out_y0, out_y2);            // #6
}